// round 1
// baseline (speedup 1.0000x reference)
#include <cuda_runtime.h>
#include <math.h>

// Problem constants
#define NN 1024   // tokens
#define DD 1024   // model dim
#define HH 16     // heads
#define CC 64     // chunk size
#define GG 16     // num chunks
#define HDIM 64   // head dim

// Scratch (device globals: no allocation allowed)
__device__ float d_Q[NN * DD];
__device__ float d_K[NN * DD];
__device__ float d_V[NN * DD];
__device__ float d_GL[NN * 32];
__device__ float d_KC[GG * DD];
__device__ float d_O[NN * DD];

// ---------------------------------------------------------------------------
// GEMM: C[M,N] = A[M,K] @ B[N,K]^T   (torch Linear semantics: x @ W.T)
// A row-major M*K, B row-major N*K, C row-major M*N. M,K multiples of 128/16.
// N may be < 128 (gate GEMM) -> guarded.
// ---------------------------------------------------------------------------
__global__ void gemm_abt(const float* __restrict__ A, const float* __restrict__ B,
                         float* __restrict__ C, int M, int N, int K)
{
    __shared__ float As[16][128];
    __shared__ float Bs[16][128];
    const int tid = threadIdx.x;
    const int bm = blockIdx.y * 128;
    const int bn = blockIdx.x * 128;
    const int tr = tid >> 4;     // 0..15
    const int tc = tid & 15;     // 0..15

    float acc[8][8];
#pragma unroll
    for (int i = 0; i < 8; ++i)
#pragma unroll
        for (int j = 0; j < 8; ++j) acc[i][j] = 0.f;

    for (int k0 = 0; k0 < K; k0 += 16) {
#pragma unroll
        for (int s = 0; s < 2; ++s) {
            int idx = tid + s * 256;
            int r = idx >> 2;              // 0..127
            int c4 = (idx & 3) << 2;       // 0,4,8,12
            float4 av = *(const float4*)(A + (size_t)(bm + r) * K + k0 + c4);
            As[c4 + 0][r] = av.x; As[c4 + 1][r] = av.y;
            As[c4 + 2][r] = av.z; As[c4 + 3][r] = av.w;
            float4 bv = make_float4(0.f, 0.f, 0.f, 0.f);
            if (bn + r < N)
                bv = *(const float4*)(B + (size_t)(bn + r) * K + k0 + c4);
            Bs[c4 + 0][r] = bv.x; Bs[c4 + 1][r] = bv.y;
            Bs[c4 + 2][r] = bv.z; Bs[c4 + 3][r] = bv.w;
        }
        __syncthreads();
#pragma unroll
        for (int kk = 0; kk < 16; ++kk) {
            float a[8], b[8];
#pragma unroll
            for (int i = 0; i < 8; ++i) a[i] = As[kk][tr * 8 + i];
#pragma unroll
            for (int j = 0; j < 8; ++j) b[j] = Bs[kk][tc * 8 + j];
#pragma unroll
            for (int i = 0; i < 8; ++i)
#pragma unroll
                for (int j = 0; j < 8; ++j)
                    acc[i][j] = fmaf(a[i], b[j], acc[i][j]);
        }
        __syncthreads();
    }

#pragma unroll
    for (int i = 0; i < 8; ++i) {
        int row = bm + tr * 8 + i;
#pragma unroll
        for (int j = 0; j < 8; ++j) {
            int col = bn + tc * 8 + j;
            if (col < N) C[(size_t)row * N + col] = acc[i][j];
        }
    }
}

// ---------------------------------------------------------------------------
// k_compress[g][d] = mean over c of K[(g*64+c)][d]   (d spans all H*HD = 1024)
// ---------------------------------------------------------------------------
__global__ void compress_kernel(const float* __restrict__ K, float* __restrict__ KC)
{
    int idx = blockIdx.x * blockDim.x + threadIdx.x;   // 16384 threads
    if (idx >= GG * DD) return;
    int g = idx >> 10;
    int d = idx & 1023;
    float s = 0.f;
#pragma unroll 8
    for (int c = 0; c < CC; ++c)
        s += K[(size_t)(g * CC + c) * DD + d];
    KC[idx] = s * (1.0f / 64.0f);
}

// ---------------------------------------------------------------------------
// Fused: selection + top-2 + inter attention + intra attention + gate blend
// grid = (G=16, H=16), 256 threads (8 warps, each owns 8 queries).
// ---------------------------------------------------------------------------
__device__ __forceinline__ float wred_max(float v) {
#pragma unroll
    for (int o = 16; o > 0; o >>= 1)
        v = fmaxf(v, __shfl_xor_sync(0xffffffffu, v, o));
    return v;
}
__device__ __forceinline__ float wred_sum(float v) {
#pragma unroll
    for (int o = 16; o > 0; o >>= 1)
        v += __shfl_xor_sync(0xffffffffu, v, o);
    return v;
}

__global__ void attn_kernel(const float* __restrict__ Q, const float* __restrict__ K,
                            const float* __restrict__ V, const float* __restrict__ KC,
                            const float* __restrict__ GL, float* __restrict__ O)
{
    extern __shared__ float sm[];
    float* q_s  = sm;              // 64*64          = 4096
    float* kc_s = q_s + 4096;      // 16*65 (padded) = 1040
    float* k_sT = kc_s + 1040;     // 64*65 (padded) = 4160  (k transposed [d][key])
    float* v_s  = k_sT + 4160;     // 64*64          = 4096  ([key][d])
    float* p_s  = v_s + 4096;      // 8*64           = 512
    float* sc_s = p_s + 512;       // 8*16           = 128
    int*   sel0 = (int*)(sc_s + 128);   // 64
    int*   sel1 = sel0 + 64;            // 64
    int*   nmask = sel1 + 64;           // 1

    const int g = blockIdx.x;
    const int h = blockIdx.y;
    const int tid = threadIdx.x;
    const int w = tid >> 5;
    const int lane = tid & 31;
    const float scale = 0.125f;   // 1/sqrt(64)

    if (tid == 0) *nmask = 0;
    // Load this chunk's Q (head h) and the compressed keys (head h)
    for (int e = tid; e < 64 * 64; e += 256) {
        int i = e >> 6, d = e & 63;
        q_s[e] = Q[(size_t)(g * 64 + i) * DD + h * 64 + d];
    }
    for (int e = tid; e < 16 * 64; e += 256) {
        int gp = e >> 6, d = e & 63;
        kc_s[gp * 65 + d] = KC[(size_t)gp * DD + h * 64 + d];
    }
    __syncthreads();

    // -------- selection: per-query scores vs 16 compressed keys, top-2 ------
    for (int qq = 0; qq < 8; ++qq) {
        int qi = w * 8 + qq;
        int gp = lane & 15;
        int half = lane >> 4;
        float part = 0.f;
#pragma unroll
        for (int d = 0; d < 32; ++d)
            part = fmaf(q_s[qi * 64 + half * 32 + d], kc_s[gp * 65 + half * 32 + d], part);
        part += __shfl_xor_sync(0xffffffffu, part, 16);
        if (lane < 16) sc_s[w * 16 + lane] = part;
        __syncwarp();
        // emulate jax.lax.top_k over masked scores: candidates are blocks > g;
        // ties (all -inf) resolve to lowest indices.
        float m1 = -INFINITY; int i1 = 0;
#pragma unroll
        for (int gp2 = 0; gp2 < 16; ++gp2) {
            float v = (gp2 > g) ? sc_s[w * 16 + gp2] : -INFINITY;
            if (v > m1) { m1 = v; i1 = gp2; }
        }
        float m2 = -INFINITY; int i2 = (i1 == 0) ? 1 : 0;
#pragma unroll
        for (int gp2 = 0; gp2 < 16; ++gp2) {
            if (gp2 == i1) continue;
            float v = (gp2 > g) ? sc_s[w * 16 + gp2] : -INFINITY;
            if (v > m2) { m2 = v; i2 = gp2; }
        }
        if (lane == 0) {
            sel0[qi] = i1; sel1[qi] = i2;
            atomicOr(nmask, (1 << i1) | (1 << i2));
        }
        __syncwarp();
    }
    __syncthreads();
    const int needed = *nmask;

    // -------- inter attention (online softmax over the 2 selected blocks) ---
    float accI0[8], accI1[8], mI[8], lI[8];
#pragma unroll
    for (int qq = 0; qq < 8; ++qq) {
        accI0[qq] = 0.f; accI1[qq] = 0.f; mI[qq] = -INFINITY; lI[qq] = 0.f;
    }

    for (int jb = 0; jb < 16; ++jb) {
        if (!(needed & (1 << jb))) continue;           // block-uniform
        __syncthreads();                               // prior consumers done
        for (int e = tid; e < 64 * 64; e += 256) {
            int c = e >> 6, d = e & 63;
            k_sT[d * 65 + c] = K[(size_t)(jb * 64 + c) * DD + h * 64 + d];
            v_s[c * 64 + d]  = V[(size_t)(jb * 64 + c) * DD + h * 64 + d];
        }
        __syncthreads();
        for (int qq = 0; qq < 8; ++qq) {
            int qi = w * 8 + qq;
            if (sel0[qi] != jb && sel1[qi] != jb) continue;  // warp-uniform
            float lg0 = 0.f, lg1 = 0.f;
#pragma unroll
            for (int d = 0; d < 64; ++d) {
                float qv = q_s[qi * 64 + d];
                lg0 = fmaf(qv, k_sT[d * 65 + lane], lg0);
                lg1 = fmaf(qv, k_sT[d * 65 + lane + 32], lg1);
            }
            lg0 *= scale; lg1 *= scale;
            float mn = wred_max(fmaxf(lg0, lg1));
            mn = fmaxf(mn, mI[qq]);
            float alpha = expf(mI[qq] - mn);           // exp(-inf)=0 first time
            float p0 = expf(lg0 - mn), p1 = expf(lg1 - mn);
            float ps = wred_sum(p0 + p1);
            lI[qq] = lI[qq] * alpha + ps;
            mI[qq] = mn;
            p_s[w * 64 + lane] = p0;
            p_s[w * 64 + lane + 32] = p1;
            __syncwarp();
            float a0 = accI0[qq] * alpha, a1 = accI1[qq] * alpha;
#pragma unroll
            for (int kk = 0; kk < 64; ++kk) {
                float p = p_s[w * 64 + kk];
                a0 = fmaf(p, v_s[kk * 64 + lane], a0);
                a1 = fmaf(p, v_s[kk * 64 + lane + 32], a1);
            }
            accI0[qq] = a0; accI1[qq] = a1;
            __syncwarp();
        }
    }

    // -------- intra attention (causal within own chunk) + blend + store -----
    __syncthreads();
    for (int e = tid; e < 64 * 64; e += 256) {
        int c = e >> 6, d = e & 63;
        k_sT[d * 65 + c] = K[(size_t)(g * 64 + c) * DD + h * 64 + d];
        v_s[c * 64 + d]  = V[(size_t)(g * 64 + c) * DD + h * 64 + d];
    }
    __syncthreads();
    for (int qq = 0; qq < 8; ++qq) {
        int qi = w * 8 + qq;
        float lg0 = 0.f, lg1 = 0.f;
#pragma unroll
        for (int d = 0; d < 64; ++d) {
            float qv = q_s[qi * 64 + d];
            lg0 = fmaf(qv, k_sT[d * 65 + lane], lg0);
            lg1 = fmaf(qv, k_sT[d * 65 + lane + 32], lg1);
        }
        lg0 = (lane      <= qi) ? lg0 * scale : -INFINITY;
        lg1 = (lane + 32 <= qi) ? lg1 * scale : -INFINITY;
        float mn = wred_max(fmaxf(lg0, lg1));          // key 0 unmasked -> finite
        float p0 = expf(lg0 - mn), p1 = expf(lg1 - mn);
        float ps = wred_sum(p0 + p1);
        p_s[w * 64 + lane] = p0;
        p_s[w * 64 + lane + 32] = p1;
        __syncwarp();
        float a0 = 0.f, a1 = 0.f;
#pragma unroll
        for (int kk = 0; kk < 64; ++kk) {
            float p = p_s[w * 64 + kk];
            a0 = fmaf(p, v_s[kk * 64 + lane], a0);
            a1 = fmaf(p, v_s[kk * 64 + lane + 32], a1);
        }
        __syncwarp();

        int n = g * 64 + qi;
        float gl0 = GL[(size_t)n * 32 + 2 * h];
        float gl1 = GL[(size_t)n * 32 + 2 * h + 1];
        float mg = fmaxf(gl0, gl1);
        float e0 = expf(gl0 - mg), e1 = expf(gl1 - mg);
        float ginv = 1.f / (e0 + e1);
        float g0 = e0 * ginv, g1 = e1 * ginv;
        float invI = 1.f / lI[qq];
        float invA = 1.f / ps;
        O[(size_t)n * DD + h * 64 + lane]      = g0 * accI0[qq] * invI + g1 * a0 * invA;
        O[(size_t)n * DD + h * 64 + lane + 32] = g0 * accI1[qq] * invI + g1 * a1 * invA;
    }
}

// ---------------------------------------------------------------------------
// Launch
// ---------------------------------------------------------------------------
extern "C" void kernel_launch(void* const* d_in, const int* in_sizes, int n_in,
                              void* d_out, int out_size)
{
    const float* x  = (const float*)d_in[0];
    const float* Wq = (const float*)d_in[1];
    const float* Wk = (const float*)d_in[2];
    const float* Wv = (const float*)d_in[3];
    const float* Wg = (const float*)d_in[4];
    const float* Wo = (const float*)d_in[5];
    float* out = (float*)d_out;

    float *Q, *K, *V, *GL, *KC, *O;
    cudaGetSymbolAddress((void**)&Q,  d_Q);
    cudaGetSymbolAddress((void**)&K,  d_K);
    cudaGetSymbolAddress((void**)&V,  d_V);
    cudaGetSymbolAddress((void**)&GL, d_GL);
    cudaGetSymbolAddress((void**)&KC, d_KC);
    cudaGetSymbolAddress((void**)&O,  d_O);

    dim3 blk(256);
    gemm_abt<<<dim3(8, 8), blk>>>(x, Wq, Q, NN, DD, DD);
    gemm_abt<<<dim3(8, 8), blk>>>(x, Wk, K, NN, DD, DD);
    gemm_abt<<<dim3(8, 8), blk>>>(x, Wv, V, NN, DD, DD);
    gemm_abt<<<dim3(1, 8), blk>>>(x, Wg, GL, NN, 32, DD);

    compress_kernel<<<(GG * DD + 255) / 256, 256>>>(K, KC);

    const int smem_bytes = 57344;
    cudaFuncSetAttribute(attn_kernel, cudaFuncAttributeMaxDynamicSharedMemorySize, smem_bytes);
    attn_kernel<<<dim3(GG, HH), 256, smem_bytes>>>(Q, K, V, KC, GL, O);

    gemm_abt<<<dim3(8, 8), blk>>>(O, Wo, out, NN, DD, DD);
}

// round 3
// speedup vs baseline: 2.0707x; 2.0707x over previous
#include <cuda_runtime.h>
#include <cuda_bf16.h>
#include <math.h>
#include <stdint.h>

#define NN 1024   // tokens
#define DD 1024   // model dim
#define HH 16     // heads
#define CC 64     // chunk size
#define GG 16     // num chunks

// ---------------- scratch (device globals; no allocation allowed) ----------
__device__ __align__(16) float d_Q[NN * DD];
__device__ __align__(16) float d_K[NN * DD];
__device__ __align__(16) float d_V[NN * DD];
__device__ __align__(16) float d_GL[NN * 32];
__device__ __align__(16) float d_KC[GG * DD];
__device__ __align__(16) float d_O[NN * DD];

__device__ __align__(16) __nv_bfloat16 sx_hi[NN * DD], sx_lo[NN * DD];
__device__ __align__(16) __nv_bfloat16 swq_hi[DD * DD], swq_lo[DD * DD];
__device__ __align__(16) __nv_bfloat16 swk_hi[DD * DD], swk_lo[DD * DD];
__device__ __align__(16) __nv_bfloat16 swv_hi[DD * DD], swv_lo[DD * DD];
__device__ __align__(16) __nv_bfloat16 swo_hi[DD * DD], swo_lo[DD * DD];
__device__ __align__(16) __nv_bfloat16 swg_hi[32 * DD], swg_lo[32 * DD];
__device__ __align__(16) __nv_bfloat16 so_hi[NN * DD], so_lo[NN * DD];

// ---------------- helpers ----------------------------------------------------
__device__ __forceinline__ uint32_t smem_u32(const void* p) {
    uint32_t a;
    asm("{ .reg .u64 t; cvta.to.shared.u64 t, %1; cvt.u32.u64 %0, t; }" : "=r"(a) : "l"(p));
    return a;
}
__device__ __forceinline__ void ldsm_x4(uint32_t* r, uint32_t addr) {
    asm volatile("ldmatrix.sync.aligned.m8n8.x4.shared.b16 {%0,%1,%2,%3}, [%4];"
                 : "=r"(r[0]), "=r"(r[1]), "=r"(r[2]), "=r"(r[3]) : "r"(addr));
}
__device__ __forceinline__ void ldsm_x2(uint32_t* r, uint32_t addr) {
    asm volatile("ldmatrix.sync.aligned.m8n8.x2.shared.b16 {%0,%1}, [%2];"
                 : "=r"(r[0]), "=r"(r[1]) : "r"(addr));
}
__device__ __forceinline__ void mma16816(float* d, const uint32_t* a, const uint32_t* b) {
    asm volatile(
        "mma.sync.aligned.m16n8k16.row.col.f32.bf16.bf16.f32 "
        "{%0,%1,%2,%3}, {%4,%5,%6,%7}, {%8,%9}, {%0,%1,%2,%3};"
        : "+f"(d[0]), "+f"(d[1]), "+f"(d[2]), "+f"(d[3])
        : "r"(a[0]), "r"(a[1]), "r"(a[2]), "r"(a[3]), "r"(b[0]), "r"(b[1]));
}

// ---------------- fp32 -> bf16 hi/lo split conversion -----------------------
struct ConvArgs {
    const float* src[6];
    __nv_bfloat16* hi[6];
    __nv_bfloat16* lo[6];
    int n[6];
};

__global__ void convert_kernel(ConvArgs a) {
    int z = blockIdx.y;
    int i4 = (blockIdx.x * blockDim.x + threadIdx.x) * 4;
    if (i4 >= a.n[z]) return;
    float4 v = *(const float4*)(a.src[z] + i4);
    __nv_bfloat16 h0 = __float2bfloat16_rn(v.x);
    __nv_bfloat16 h1 = __float2bfloat16_rn(v.y);
    __nv_bfloat16 h2 = __float2bfloat16_rn(v.z);
    __nv_bfloat16 h3 = __float2bfloat16_rn(v.w);
    __nv_bfloat16 l0 = __float2bfloat16_rn(v.x - __bfloat162float(h0));
    __nv_bfloat16 l1 = __float2bfloat16_rn(v.y - __bfloat162float(h1));
    __nv_bfloat16 l2 = __float2bfloat16_rn(v.z - __bfloat162float(h2));
    __nv_bfloat16 l3 = __float2bfloat16_rn(v.w - __bfloat162float(h3));
    uint2 hp, lp;
    hp.x = (uint32_t)__bfloat16_as_ushort(h0) | ((uint32_t)__bfloat16_as_ushort(h1) << 16);
    hp.y = (uint32_t)__bfloat16_as_ushort(h2) | ((uint32_t)__bfloat16_as_ushort(h3) << 16);
    lp.x = (uint32_t)__bfloat16_as_ushort(l0) | ((uint32_t)__bfloat16_as_ushort(l1) << 16);
    lp.y = (uint32_t)__bfloat16_as_ushort(l2) | ((uint32_t)__bfloat16_as_ushort(l3) << 16);
    *(uint2*)(a.hi[z] + i4) = hp;
    *(uint2*)(a.lo[z] + i4) = lp;
}

// ---------------- HMMA GEMM: C[M,Nz] = A[M,K] @ B[Nz,K]^T -------------------
// bf16x3 emulation: C = Ah*Bh + Ah*Bl + Al*Bh, fp32 accumulators.
// 128x128 CTA tile, 8 warps (2x4), warp tile 64x32, mma.sync m16n8k16.
struct GemmArgs {
    const __nv_bfloat16* Ahi;
    const __nv_bfloat16* Alo;
    const __nv_bfloat16* Bhi[4];
    const __nv_bfloat16* Blo[4];
    float* C[4];
    int N[4];
};

#define SPAD 40   // bf16 elements per smem row (32 data + 8 pad) -> 80B stride

__global__ void __launch_bounds__(256) mma_gemm(GemmArgs g) {
    const int z = blockIdx.z;
    const int Nz = g.N[z];
    const int bn = blockIdx.x * 128;
    if (bn >= Nz) return;
    const int bm = blockIdx.y * 128;
    const int ncols = (Nz - bn < 128) ? (Nz - bn) : 128;

    __shared__ __nv_bfloat16 As_h[128 * SPAD];
    __shared__ __nv_bfloat16 As_l[128 * SPAD];
    __shared__ __nv_bfloat16 Bs_h[128 * SPAD];
    __shared__ __nv_bfloat16 Bs_l[128 * SPAD];

    const int tid = threadIdx.x;
    const int wid = tid >> 5;
    const int lane = tid & 31;
    const int wm = wid >> 2;        // 0..1 -> 64-row slab
    const int wn = wid & 3;         // 0..3 -> 32-col slab
    const bool active = (wn * 32) < ncols;

    float acc[4][4][4];
#pragma unroll
    for (int mt = 0; mt < 4; ++mt)
#pragma unroll
        for (int nt = 0; nt < 4; ++nt)
#pragma unroll
            for (int e = 0; e < 4; ++e) acc[mt][nt][e] = 0.f;

    const __nv_bfloat16* Ah = g.Ahi + (size_t)bm * DD;
    const __nv_bfloat16* Al = g.Alo + (size_t)bm * DD;
    const __nv_bfloat16* Bh = g.Bhi[z] + (size_t)bn * DD;
    const __nv_bfloat16* Bl = g.Blo[z] + (size_t)bn * DD;

    const uint32_t sAh = smem_u32(As_h), sAl = smem_u32(As_l);
    const uint32_t sBh = smem_u32(Bs_h), sBl = smem_u32(Bs_l);

    // ldmatrix addressing (precomputed, bytes)
    const int a_row = wm * 64 + (lane & 15);
    const int a_kof = (lane >> 4) << 3;                  // 0 or 8
    const int b_row = wn * 32 + (lane & 7);
    const int b_kof = (lane & 8) ? 8 : 0;

    for (int k0 = 0; k0 < DD; k0 += 32) {
        // stage 4 tiles of 128x32 bf16
#pragma unroll
        for (int s = 0; s < 2; ++s) {
            int u = tid + s * 256;                        // 0..511
            int r = u >> 2, seg = (u & 3) << 3;           // seg in bf16 elems
            size_t go = (size_t)r * DD + k0 + seg;
            uint32_t so = (uint32_t)(r * SPAD + seg);
            *(uint4*)(As_h + so) = *(const uint4*)(Ah + go);
            *(uint4*)(As_l + so) = *(const uint4*)(Al + go);
            if (r < ncols) {
                *(uint4*)(Bs_h + so) = *(const uint4*)(Bh + go);
                *(uint4*)(Bs_l + so) = *(const uint4*)(Bl + go);
            }
        }
        __syncthreads();
        if (active) {
#pragma unroll
            for (int kk = 0; kk < 32; kk += 16) {
                uint32_t ah[4][4], al[4][4], bh[4][2], bl[4][2];
#pragma unroll
                for (int mt = 0; mt < 4; ++mt) {
                    uint32_t off = (uint32_t)(((a_row + mt * 16) * SPAD + kk + a_kof) * 2);
                    ldsm_x4(ah[mt], sAh + off);
                    ldsm_x4(al[mt], sAl + off);
                }
#pragma unroll
                for (int nt = 0; nt < 4; ++nt) {
                    uint32_t off = (uint32_t)(((b_row + nt * 8) * SPAD + kk + b_kof) * 2);
                    ldsm_x2(bh[nt], sBh + off);
                    ldsm_x2(bl[nt], sBl + off);
                }
#pragma unroll
                for (int mt = 0; mt < 4; ++mt)
#pragma unroll
                    for (int nt = 0; nt < 4; ++nt) {
                        mma16816(acc[mt][nt], ah[mt], bh[nt]);
                        mma16816(acc[mt][nt], ah[mt], bl[nt]);
                        mma16816(acc[mt][nt], al[mt], bh[nt]);
                    }
            }
        }
        __syncthreads();
    }

    // epilogue
    float* Cz = g.C[z];
#pragma unroll
    for (int mt = 0; mt < 4; ++mt) {
        int row0 = bm + wm * 64 + mt * 16 + (lane >> 2);
#pragma unroll
        for (int nt = 0; nt < 4; ++nt) {
            int col = bn + wn * 32 + nt * 8 + (lane & 3) * 2;
            if (col < Nz) {
                *(float2*)(Cz + (size_t)row0 * Nz + col) =
                    make_float2(acc[mt][nt][0], acc[mt][nt][1]);
                *(float2*)(Cz + (size_t)(row0 + 8) * Nz + col) =
                    make_float2(acc[mt][nt][2], acc[mt][nt][3]);
            }
        }
    }
}

// ---------------- k_compress ------------------------------------------------
__global__ void compress_kernel(const float* __restrict__ K, float* __restrict__ KC)
{
    int idx = blockIdx.x * blockDim.x + threadIdx.x;
    if (idx >= GG * DD) return;
    int g = idx >> 10;
    int d = idx & 1023;
    float s = 0.f;
#pragma unroll 8
    for (int c = 0; c < CC; ++c)
        s += K[(size_t)(g * CC + c) * DD + d];
    KC[idx] = s * (1.0f / 64.0f);
}

// ---------------- fused sparse attention (as in R1, passing) ----------------
__device__ __forceinline__ float wred_max(float v) {
#pragma unroll
    for (int o = 16; o > 0; o >>= 1)
        v = fmaxf(v, __shfl_xor_sync(0xffffffffu, v, o));
    return v;
}
__device__ __forceinline__ float wred_sum(float v) {
#pragma unroll
    for (int o = 16; o > 0; o >>= 1)
        v += __shfl_xor_sync(0xffffffffu, v, o);
    return v;
}

__global__ void attn_kernel(const float* __restrict__ Q, const float* __restrict__ K,
                            const float* __restrict__ V, const float* __restrict__ KC,
                            const float* __restrict__ GL, float* __restrict__ O)
{
    extern __shared__ float sm[];
    float* q_s  = sm;              // 64*64
    float* kc_s = q_s + 4096;      // 16*65
    float* k_sT = kc_s + 1040;     // 64*65
    float* v_s  = k_sT + 4160;     // 64*64
    float* p_s  = v_s + 4096;      // 8*64
    float* sc_s = p_s + 512;       // 8*16
    int*   sel0 = (int*)(sc_s + 128);
    int*   sel1 = sel0 + 64;
    int*   nmask = sel1 + 64;

    const int g = blockIdx.x;
    const int h = blockIdx.y;
    const int tid = threadIdx.x;
    const int w = tid >> 5;
    const int lane = tid & 31;
    const float scale = 0.125f;

    if (tid == 0) *nmask = 0;
    for (int e = tid; e < 64 * 64; e += 256) {
        int i = e >> 6, d = e & 63;
        q_s[e] = Q[(size_t)(g * 64 + i) * DD + h * 64 + d];
    }
    for (int e = tid; e < 16 * 64; e += 256) {
        int gp = e >> 6, d = e & 63;
        kc_s[gp * 65 + d] = KC[(size_t)gp * DD + h * 64 + d];
    }
    __syncthreads();

    for (int qq = 0; qq < 8; ++qq) {
        int qi = w * 8 + qq;
        int gp = lane & 15;
        int half = lane >> 4;
        float part = 0.f;
#pragma unroll
        for (int d = 0; d < 32; ++d)
            part = fmaf(q_s[qi * 64 + half * 32 + d], kc_s[gp * 65 + half * 32 + d], part);
        part += __shfl_xor_sync(0xffffffffu, part, 16);
        if (lane < 16) sc_s[w * 16 + lane] = part;
        __syncwarp();
        float m1 = -INFINITY; int i1 = 0;
#pragma unroll
        for (int gp2 = 0; gp2 < 16; ++gp2) {
            float v = (gp2 > g) ? sc_s[w * 16 + gp2] : -INFINITY;
            if (v > m1) { m1 = v; i1 = gp2; }
        }
        float m2 = -INFINITY; int i2 = (i1 == 0) ? 1 : 0;
#pragma unroll
        for (int gp2 = 0; gp2 < 16; ++gp2) {
            if (gp2 == i1) continue;
            float v = (gp2 > g) ? sc_s[w * 16 + gp2] : -INFINITY;
            if (v > m2) { m2 = v; i2 = gp2; }
        }
        if (lane == 0) {
            sel0[qi] = i1; sel1[qi] = i2;
            atomicOr(nmask, (1 << i1) | (1 << i2));
        }
        __syncwarp();
    }
    __syncthreads();
    const int needed = *nmask;

    float accI0[8], accI1[8], mI[8], lI[8];
#pragma unroll
    for (int qq = 0; qq < 8; ++qq) {
        accI0[qq] = 0.f; accI1[qq] = 0.f; mI[qq] = -INFINITY; lI[qq] = 0.f;
    }

    for (int jb = 0; jb < 16; ++jb) {
        if (!(needed & (1 << jb))) continue;
        __syncthreads();
        for (int e = tid; e < 64 * 64; e += 256) {
            int c = e >> 6, d = e & 63;
            k_sT[d * 65 + c] = K[(size_t)(jb * 64 + c) * DD + h * 64 + d];
            v_s[c * 64 + d]  = V[(size_t)(jb * 64 + c) * DD + h * 64 + d];
        }
        __syncthreads();
        for (int qq = 0; qq < 8; ++qq) {
            int qi = w * 8 + qq;
            if (sel0[qi] != jb && sel1[qi] != jb) continue;
            float lg0 = 0.f, lg1 = 0.f;
#pragma unroll
            for (int d = 0; d < 64; ++d) {
                float qv = q_s[qi * 64 + d];
                lg0 = fmaf(qv, k_sT[d * 65 + lane], lg0);
                lg1 = fmaf(qv, k_sT[d * 65 + lane + 32], lg1);
            }
            lg0 *= scale; lg1 *= scale;
            float mn = wred_max(fmaxf(lg0, lg1));
            mn = fmaxf(mn, mI[qq]);
            float alpha = expf(mI[qq] - mn);
            float p0 = expf(lg0 - mn), p1 = expf(lg1 - mn);
            float ps = wred_sum(p0 + p1);
            lI[qq] = lI[qq] * alpha + ps;
            mI[qq] = mn;
            p_s[w * 64 + lane] = p0;
            p_s[w * 64 + lane + 32] = p1;
            __syncwarp();
            float a0 = accI0[qq] * alpha, a1 = accI1[qq] * alpha;
#pragma unroll
            for (int kk = 0; kk < 64; ++kk) {
                float p = p_s[w * 64 + kk];
                a0 = fmaf(p, v_s[kk * 64 + lane], a0);
                a1 = fmaf(p, v_s[kk * 64 + lane + 32], a1);
            }
            accI0[qq] = a0; accI1[qq] = a1;
            __syncwarp();
        }
    }

    __syncthreads();
    for (int e = tid; e < 64 * 64; e += 256) {
        int c = e >> 6, d = e & 63;
        k_sT[d * 65 + c] = K[(size_t)(g * 64 + c) * DD + h * 64 + d];
        v_s[c * 64 + d]  = V[(size_t)(g * 64 + c) * DD + h * 64 + d];
    }
    __syncthreads();
    for (int qq = 0; qq < 8; ++qq) {
        int qi = w * 8 + qq;
        float lg0 = 0.f, lg1 = 0.f;
#pragma unroll
        for (int d = 0; d < 64; ++d) {
            float qv = q_s[qi * 64 + d];
            lg0 = fmaf(qv, k_sT[d * 65 + lane], lg0);
            lg1 = fmaf(qv, k_sT[d * 65 + lane + 32], lg1);
        }
        lg0 = (lane      <= qi) ? lg0 * scale : -INFINITY;
        lg1 = (lane + 32 <= qi) ? lg1 * scale : -INFINITY;
        float mn = wred_max(fmaxf(lg0, lg1));
        float p0 = expf(lg0 - mn), p1 = expf(lg1 - mn);
        float ps = wred_sum(p0 + p1);
        p_s[w * 64 + lane] = p0;
        p_s[w * 64 + lane + 32] = p1;
        __syncwarp();
        float a0 = 0.f, a1 = 0.f;
#pragma unroll
        for (int kk = 0; kk < 64; ++kk) {
            float p = p_s[w * 64 + kk];
            a0 = fmaf(p, v_s[kk * 64 + lane], a0);
            a1 = fmaf(p, v_s[kk * 64 + lane + 32], a1);
        }
        __syncwarp();

        int n = g * 64 + qi;
        float gl0 = GL[(size_t)n * 32 + 2 * h];
        float gl1 = GL[(size_t)n * 32 + 2 * h + 1];
        float mg = fmaxf(gl0, gl1);
        float e0 = expf(gl0 - mg), e1 = expf(gl1 - mg);
        float ginv = 1.f / (e0 + e1);
        float g0 = e0 * ginv, g1 = e1 * ginv;
        float invI = 1.f / lI[qq];
        float invA = 1.f / ps;
        O[(size_t)n * DD + h * 64 + lane]      = g0 * accI0[qq] * invI + g1 * a0 * invA;
        O[(size_t)n * DD + h * 64 + lane + 32] = g0 * accI1[qq] * invI + g1 * a1 * invA;
    }
}

// ---------------- launch -----------------------------------------------------
extern "C" void kernel_launch(void* const* d_in, const int* in_sizes, int n_in,
                              void* d_out, int out_size)
{
    const float* x  = (const float*)d_in[0];
    const float* Wq = (const float*)d_in[1];
    const float* Wk = (const float*)d_in[2];
    const float* Wv = (const float*)d_in[3];
    const float* Wg = (const float*)d_in[4];
    const float* Wo = (const float*)d_in[5];
    float* out = (float*)d_out;

    float *Q, *K, *V, *GL, *KC, *O;
    cudaGetSymbolAddress((void**)&Q,  d_Q);
    cudaGetSymbolAddress((void**)&K,  d_K);
    cudaGetSymbolAddress((void**)&V,  d_V);
    cudaGetSymbolAddress((void**)&GL, d_GL);
    cudaGetSymbolAddress((void**)&KC, d_KC);
    cudaGetSymbolAddress((void**)&O,  d_O);

    __nv_bfloat16 *xh, *xl, *qh, *ql, *kh, *kl, *vh, *vl, *oh, *ol, *gh, *gl2, *obh, *obl;
    cudaGetSymbolAddress((void**)&xh,  sx_hi);  cudaGetSymbolAddress((void**)&xl,  sx_lo);
    cudaGetSymbolAddress((void**)&qh,  swq_hi); cudaGetSymbolAddress((void**)&ql,  swq_lo);
    cudaGetSymbolAddress((void**)&kh,  swk_hi); cudaGetSymbolAddress((void**)&kl,  swk_lo);
    cudaGetSymbolAddress((void**)&vh,  swv_hi); cudaGetSymbolAddress((void**)&vl,  swv_lo);
    cudaGetSymbolAddress((void**)&oh,  swo_hi); cudaGetSymbolAddress((void**)&ol,  swo_lo);
    cudaGetSymbolAddress((void**)&gh,  swg_hi); cudaGetSymbolAddress((void**)&gl2, swg_lo);
    cudaGetSymbolAddress((void**)&obh, so_hi);  cudaGetSymbolAddress((void**)&obl, so_lo);

    // 1) split-convert x + all weights
    ConvArgs ca;
    ca.src[0] = x;  ca.hi[0] = xh;  ca.lo[0] = xl;  ca.n[0] = NN * DD;
    ca.src[1] = Wq; ca.hi[1] = qh;  ca.lo[1] = ql;  ca.n[1] = DD * DD;
    ca.src[2] = Wk; ca.hi[2] = kh;  ca.lo[2] = kl;  ca.n[2] = DD * DD;
    ca.src[3] = Wv; ca.hi[3] = vh;  ca.lo[3] = vl;  ca.n[3] = DD * DD;
    ca.src[4] = Wg; ca.hi[4] = gh;  ca.lo[4] = gl2; ca.n[4] = 32 * DD;
    ca.src[5] = Wo; ca.hi[5] = oh;  ca.lo[5] = ol;  ca.n[5] = DD * DD;
    convert_kernel<<<dim3(1024, 6), 256>>>(ca);

    // 2) QKV + gate projections, one launch
    GemmArgs gq;
    gq.Ahi = xh; gq.Alo = xl;
    gq.Bhi[0] = qh; gq.Blo[0] = ql;  gq.C[0] = Q;  gq.N[0] = DD;
    gq.Bhi[1] = kh; gq.Blo[1] = kl;  gq.C[1] = K;  gq.N[1] = DD;
    gq.Bhi[2] = vh; gq.Blo[2] = vl;  gq.C[2] = V;  gq.N[2] = DD;
    gq.Bhi[3] = gh; gq.Blo[3] = gl2; gq.C[3] = GL; gq.N[3] = 32;
    mma_gemm<<<dim3(8, 8, 4), 256>>>(gq);

    // 3) compressed block keys
    compress_kernel<<<(GG * DD + 255) / 256, 256>>>(K, KC);

    // 4) fused sparse attention
    const int ASMEM = 57344;
    cudaFuncSetAttribute(attn_kernel, cudaFuncAttributeMaxDynamicSharedMemorySize, ASMEM);
    attn_kernel<<<dim3(GG, HH), 256, ASMEM>>>(Q, K, V, KC, GL, O);

    // 5) split-convert O
    ConvArgs co;
    co.src[0] = O; co.hi[0] = obh; co.lo[0] = obl; co.n[0] = NN * DD;
    for (int i = 1; i < 6; ++i) { co.src[i] = O; co.hi[i] = obh; co.lo[i] = obl; co.n[i] = 0; }
    convert_kernel<<<dim3(1024, 1), 256>>>(co);

    // 6) output projection
    GemmArgs go;
    go.Ahi = obh; go.Alo = obl;
    go.Bhi[0] = oh; go.Blo[0] = ol; go.C[0] = out; go.N[0] = DD;
    for (int i = 1; i < 4; ++i) { go.Bhi[i] = oh; go.Blo[i] = ol; go.C[i] = out; go.N[i] = 0; }
    mma_gemm<<<dim3(8, 8, 1), 256>>>(go);
}